// round 16
// baseline (speedup 1.0000x reference)
#include <cuda_runtime.h>
#include <cuda_fp16.h>
#include <math.h>
#include <stdint.h>

#define D_IN   768
#define D_OUT  256
#define NEXP   8
#define NT_MAX 32768
#define NCTAS  296                 // 148 SMs x 2

// ---------------- device scratch (no allocs; zero-initialized at load) -------
__device__ int    g_cnt[NEXP];
__device__ int    g_ticket;
__device__ int    g_done;
__device__ int    g_tok[NEXP * NT_MAX];
__device__ float  g_wt [NEXP * NT_MAX];
__device__ __half g_xh [NT_MAX * D_IN];              // x in fp16 (48 MB)
__device__ __half g_Wh [NEXP * D_OUT * D_IN];        // W in fp16, transposed [e][n][k]

__device__ __forceinline__ uint32_t smem_u32(const void* p) {
    uint32_t a;
    asm("{ .reg .u64 t; cvta.to.shared.u64 t, %1; cvt.u32.u64 %0, t; }" : "=r"(a) : "l"(p));
    return a;
}

// ---------------- kernel 1 (merged): convert W  +  gate + zero-out ----------
// R15 form, 2 tokens per warp in parallel (one weight LDS feeds both tokens).
#define CONV_BLOCKS (NEXP * (D_IN / 32) * (D_OUT / 32))   // 1536
#define GW_PITCH 772

__global__ __launch_bounds__(256)
void prep_kernel(const float* __restrict__ x,
                 const float* __restrict__ gW,
                 const float* __restrict__ gb,
                 const float* __restrict__ eW,
                 float* __restrict__ out,
                 int NT) {
    const int tid = threadIdx.x;

    if (blockIdx.x < CONV_BLOCKS) {
        __shared__ float t[32][33];
        int idx = blockIdx.x;
        int e   = idx / 192;
        int rem = idx - e * 192;
        int k0  = (rem >> 3) * 32;
        int n0  = (rem & 7) * 32;
        int tx = tid & 31, ty = tid >> 5;   // 32 x 8
        const float* W = eW + (size_t)e * D_IN * D_OUT;
        __half* Wh = g_Wh + (size_t)e * D_OUT * D_IN;
#pragma unroll
        for (int j = 0; j < 4; j++)
            t[ty + j * 8][tx] = W[(size_t)(k0 + ty + j * 8) * D_OUT + n0 + tx];
        __syncthreads();
#pragma unroll
        for (int j = 0; j < 4; j++)
            Wh[(size_t)(n0 + ty + j * 8) * D_IN + k0 + tx] =
                __float2half_rn(t[tx][ty + j * 8]);
        return;
    }

    __shared__ float sWt[NEXP * GW_PITCH];   // transposed [e][k], padded pitch
    for (int i = tid; i < D_IN * NEXP; i += 256)
        sWt[(i & 7) * GW_PITCH + (i >> 3)] = gW[i];
    __syncthreads();

    const int warp = tid >> 5, lane = tid & 31;
    const int tok0 = (blockIdx.x - CONV_BLOCKS) * 16 + warp * 2;
    if (tok0 >= NT) return;          // NT multiple of 16 -> both tokens valid

    // zero both tokens' output rows (256 floats each): 2 x float4 per lane
    {
        float4 z = make_float4(0.f, 0.f, 0.f, 0.f);
#pragma unroll
        for (int t = 0; t < 2; t++) {
            float4* orow = (float4*)(out + (size_t)(tok0 + t) * D_OUT);
            orow[lane]      = z;
            orow[lane + 32] = z;
        }
    }

    const float4* xr0 = (const float4*)(x + (size_t)tok0 * D_IN);
    const float4* xr1 = (const float4*)(x + (size_t)(tok0 + 1) * D_IN);
    uint2* xo0 = (uint2*)(g_xh + (size_t)tok0 * D_IN);
    uint2* xo1 = (uint2*)(g_xh + (size_t)(tok0 + 1) * D_IN);

    float acc[2][NEXP];
#pragma unroll
    for (int t = 0; t < 2; t++)
#pragma unroll
        for (int e = 0; e < NEXP; e++) acc[t][e] = 0.f;

#pragma unroll
    for (int j = 0; j < D_IN / 128; j++) {      // 6 iters
        const int idx = lane + j * 32;           // float4 index
        float4 v0 = xr0[idx];
        float4 v1 = xr1[idx];
        const int k = idx * 4;
#pragma unroll
        for (int e = 0; e < NEXP; e++) {
            const float* w = &sWt[e * GW_PITCH + k];
            acc[0][e] = fmaf(v0.x, w[0], acc[0][e]);
            acc[0][e] = fmaf(v0.y, w[1], acc[0][e]);
            acc[0][e] = fmaf(v0.z, w[2], acc[0][e]);
            acc[0][e] = fmaf(v0.w, w[3], acc[0][e]);
            acc[1][e] = fmaf(v1.x, w[0], acc[1][e]);
            acc[1][e] = fmaf(v1.y, w[1], acc[1][e]);
            acc[1][e] = fmaf(v1.z, w[2], acc[1][e]);
            acc[1][e] = fmaf(v1.w, w[3], acc[1][e]);
        }
        __half2 a0 = __floats2half2_rn(v0.x, v0.y);
        __half2 a1 = __floats2half2_rn(v0.z, v0.w);
        __half2 b0 = __floats2half2_rn(v1.x, v1.y);
        __half2 b1 = __floats2half2_rn(v1.z, v1.w);
        uint2 ua, ub;
        ua.x = *(uint32_t*)&a0;  ua.y = *(uint32_t*)&a1;
        ub.x = *(uint32_t*)&b0;  ub.y = *(uint32_t*)&b1;
        xo0[idx] = ua;
        xo1[idx] = ub;
    }

#pragma unroll
    for (int off = 16; off > 0; off >>= 1)
#pragma unroll
        for (int t = 0; t < 2; t++)
#pragma unroll
            for (int e = 0; e < NEXP; e++)
                acc[t][e] += __shfl_xor_sync(0xffffffffu, acc[t][e], off);

    if (lane == 0) {
#pragma unroll
        for (int t = 0; t < 2; t++) {
            const int token = tok0 + t;
            float l[NEXP];
#pragma unroll
            for (int e = 0; e < NEXP; e++) l[e] = acc[t][e] + gb[e];
            float m = l[0];
#pragma unroll
            for (int e = 1; e < NEXP; e++) m = fmaxf(m, l[e]);
            float s = 0.f, w[NEXP];
#pragma unroll
            for (int e = 0; e < NEXP; e++) { w[e] = __expf(l[e] - m); s += w[e]; }
            float inv = 1.f / s;
            int i0 = 0;
#pragma unroll
            for (int e = 1; e < NEXP; e++) if (l[e] > l[i0]) i0 = e;
            int i1 = (i0 == 0) ? 1 : 0;
#pragma unroll
            for (int e = 0; e < NEXP; e++) if (e != i0 && l[e] > l[i1]) i1 = e;

            int p0 = atomicAdd(&g_cnt[i0], 1);
            g_tok[i0 * NT_MAX + p0] = token;  g_wt[i0 * NT_MAX + p0] = w[i0] * inv;
            int p1 = atomicAdd(&g_cnt[i1], 1);
            g_tok[i1 * NT_MAX + p1] = token;  g_wt[i1 * NT_MAX + p1] = w[i1] * inv;
        }
    }
}

// ---------------- kernel 2: persistent FP16 GEMM (exact R10 — frozen) -------
#define BKS      64
#define NSTAGE   (D_IN / BKS)     // 12
#define PSTAGES  3
#define A_STAGE  18432            // 128 * 144
#define B_STAGE  18432
#define STAGE_SZ (A_STAGE + B_STAGE)
#define SM_SZ    (PSTAGES * STAGE_SZ)             // 110592

#define CP_ASYNC_Z(dst, src, sz) \
    asm volatile("cp.async.cg.shared.global [%0], [%1], 16, %2;" \
                 :: "r"(dst), "l"(src), "r"(sz) : "memory")
#define CP_ASYNC16(dst, src) \
    asm volatile("cp.async.cg.shared.global [%0], [%1], 16;" \
                 :: "r"(dst), "l"(src) : "memory")
#define CP_COMMIT()  asm volatile("cp.async.commit_group;" ::: "memory")
#define CP_WAIT(n)   asm volatile("cp.async.wait_group %0;" :: "n"(n) : "memory")

#define LDSM_X4(r0, r1, r2, r3, addr) \
    asm volatile("ldmatrix.sync.aligned.m8n8.x4.shared.b16 {%0,%1,%2,%3}, [%4];" \
                 : "=r"(r0), "=r"(r1), "=r"(r2), "=r"(r3) : "r"(addr))

__global__ __launch_bounds__(256, 2)
void moe_gemm_f16(const float* __restrict__ eb, float* __restrict__ out) {
    extern __shared__ __align__(1024) char smem[];
    const uint32_t sb = smem_u32(smem);
    __shared__ int sTicket;

    const int tid  = threadIdx.x;
    const int wid  = tid >> 5;
    const int lane = tid & 31;
    const int wm = wid >> 1, wn = wid & 1;        // 4m x 2n
    const int grp = lane >> 2, tig = lane & 3;

    int cnts[NEXP], pfx[NEXP + 1];
    pfx[0] = 0;
#pragma unroll
    for (int e = 0; e < NEXP; e++) {
        cnts[e] = g_cnt[e];
        pfx[e + 1] = pfx[e] + 2 * ((cnts[e] + 127) >> 7);
    }
    const int totalTiles = pfx[NEXP];

    const uint32_t aRow = (uint32_t)(wm * 32 + (lane & 15));
    const uint32_t aCol = (uint32_t)((lane >> 4) * 8);
    const uint32_t bRow = (uint32_t)(wn * 64 + (lane & 7) + (lane >> 4) * 8);
    const uint32_t bCol = (uint32_t)(((lane >> 3) & 1) * 8);

    const char* xhBase = (const char*)g_xh;
    const char* whBase = (const char*)g_Wh;

    uint32_t aoff[4], adst[4], asz[4], boff[4], bdst[4];

    auto setupTile = [&](int ticket, int& e, int& mbase, int& nbase, int& cnt) {
        e = 0;
#pragma unroll
        for (int k = 1; k < NEXP; k++) if (ticket >= pfx[k]) e = k;
        const int local = ticket - pfx[e];
        nbase = (local & 1) * 128;
        mbase = (local >> 1) * 128;
        cnt   = cnts[e];
#pragma unroll
        for (int i = 0; i < 4; i++) {
            int c = tid + i * 256;
            int r = c >> 3, q = c & 7;
            int grow = mbase + r;
            bool v = grow < cnt;
            aoff[i] = (uint32_t)((v ? (size_t)g_tok[e * NT_MAX + grow] * D_IN : 0) * 2 + q * 16);
            adst[i] = sb + (uint32_t)(r * 144 + q * 16);
            asz[i]  = v ? 16u : 0u;
        }
#pragma unroll
        for (int i = 0; i < 4; i++) {
            int c = tid + i * 256;
            int n = c >> 3, q = c & 7;
            boff[i] = (uint32_t)((((size_t)e * D_OUT + nbase + n) * D_IN) * 2 + q * 16);
            bdst[i] = sb + (uint32_t)(A_STAGE + n * 144 + q * 16);
        }
    };
    auto issue = [&](int s, int sl) {
        const uint32_t so = (uint32_t)(sl * STAGE_SZ);
        const uint32_t k0 = (uint32_t)(s * BKS * 2);
#pragma unroll
        for (int i = 0; i < 4; i++)
            CP_ASYNC_Z(adst[i] + so, xhBase + aoff[i] + k0, asz[i]);
#pragma unroll
        for (int i = 0; i < 4; i++)
            CP_ASYNC16(bdst[i] + so, whBase + boff[i] + k0);
    };

    if (tid == 0) sTicket = atomicAdd(&g_ticket, 1);
    __syncthreads();
    int ticket = sTicket;
    int curE = 0, curM = 0, curN = 0, curCnt = 0;
    bool have = ticket < totalTiles;
    if (have) {
        setupTile(ticket, curE, curM, curN, curCnt);
        issue(0, 0); CP_COMMIT();
        issue(1, 1); CP_COMMIT();
    }

    while (have) {
        float acc[2][8][4];
#pragma unroll
        for (int mi = 0; mi < 2; mi++)
#pragma unroll
            for (int ni = 0; ni < 8; ni++)
#pragma unroll
                for (int c = 0; c < 4; c++) acc[mi][ni][c] = 0.f;

        int slot = 0, wslot = PSTAGES - 1;
        for (int t = 0; t < NSTAGE; t++) {
            CP_WAIT(PSTAGES - 2);
            __syncthreads();

            const uint32_t aBase = sb + (uint32_t)(slot * STAGE_SZ);
            const uint32_t bBase = aBase + A_STAGE;

#pragma unroll
            for (int kk = 0; kk < BKS; kk += 16) {
                uint32_t a[2][4];
#pragma unroll
                for (int mi = 0; mi < 2; mi++) {
                    uint32_t addr = aBase + (aRow + mi * 16) * 144 + (aCol + kk) * 2;
                    LDSM_X4(a[mi][0], a[mi][1], a[mi][2], a[mi][3], addr);
                }
                uint32_t b[8][2];
#pragma unroll
                for (int nip = 0; nip < 4; nip++) {
                    uint32_t addr = bBase + (bRow + nip * 16) * 144 + (bCol + kk) * 2;
                    LDSM_X4(b[nip*2][0], b[nip*2][1], b[nip*2+1][0], b[nip*2+1][1], addr);
                }
#pragma unroll
                for (int ni = 0; ni < 8; ni++)
#pragma unroll
                    for (int mi = 0; mi < 2; mi++) {
                        asm volatile(
                            "mma.sync.aligned.m16n8k16.row.col.f32.f16.f16.f32 "
                            "{%0,%1,%2,%3}, {%4,%5,%6,%7}, {%8,%9}, {%0,%1,%2,%3};"
                            : "+f"(acc[mi][ni][0]), "+f"(acc[mi][ni][1]),
                              "+f"(acc[mi][ni][2]), "+f"(acc[mi][ni][3])
                            : "r"(a[mi][0]), "r"(a[mi][1]), "r"(a[mi][2]), "r"(a[mi][3]),
                              "r"(b[ni][0]), "r"(b[ni][1]));
                    }
            }

            if (t + PSTAGES - 1 < NSTAGE) issue(t + PSTAGES - 1, wslot);
            CP_COMMIT();
            if (++slot == PSTAGES) slot = 0;
            if (++wslot == PSTAGES) wslot = 0;
        }

        // claim next tile; prefetch its prologue BEFORE the epilogue.
        __syncthreads();
        if (tid == 0) sTicket = atomicAdd(&g_ticket, 1);
        __syncthreads();
        int nextTicket = sTicket;
        bool haveNext = nextTicket < totalTiles;
        int nE = 0, nM = 0, nN = 0, nCnt = 0;
        if (haveNext) {
            setupTile(nextTicket, nE, nM, nN, nCnt);
            issue(0, 0); CP_COMMIT();
            issue(1, 1); CP_COMMIT();
        }

        // epilogue for current tile (overlaps next-tile DRAM latency)
        {
            float2 bias[8];
#pragma unroll
            for (int ni = 0; ni < 8; ni++)
                bias[ni] = *(const float2*)(eb + curE * D_OUT + curN + wn * 64 + ni * 8 + tig * 2);

#pragma unroll
            for (int mi = 0; mi < 2; mi++) {
#pragma unroll
                for (int h = 0; h < 2; h++) {
                    int grow = curM + wm * 32 + mi * 16 + grp + h * 8;
                    bool valid = grow < curCnt;
                    int   token = valid ? g_tok[curE * NT_MAX + grow] : 0;
                    float w     = valid ? g_wt [curE * NT_MAX + grow] : 0.f;
                    float* orow = out + (size_t)token * D_OUT + curN + wn * 64;
#pragma unroll
                    for (int ni = 0; ni < 8; ni++) {
                        float v0 = w * (acc[mi][ni][h * 2]     + bias[ni].x);
                        float v1 = w * (acc[mi][ni][h * 2 + 1] + bias[ni].y);
                        float p0 = __shfl_xor_sync(0xffffffffu, v0, 1);
                        float p1 = __shfl_xor_sync(0xffffffffu, v1, 1);
                        if (valid && !(tig & 1)) {
                            asm volatile("red.global.add.v4.f32 [%0], {%1, %2, %3, %4};"
                                         :: "l"(orow + ni * 8 + (tig & 2) * 2),
                                            "f"(v0), "f"(v1), "f"(p0), "f"(p1) : "memory");
                        }
                    }
                }
            }
        }

        curE = nE; curM = nM; curN = nN; curCnt = nCnt;
        have = haveNext;
    }

    // self-reset for next graph replay: last CTA clears state.
    __syncthreads();
    if (tid == 0) {
        int d = atomicAdd(&g_done, 1);
        if (d == NCTAS - 1) {
#pragma unroll
            for (int e = 0; e < NEXP; e++) g_cnt[e] = 0;
            g_ticket = 0;
            g_done = 0;
        }
    }
}

// ---------------- launch ----------------
extern "C" void kernel_launch(void* const* d_in, const int* in_sizes, int n_in,
                              void* d_out, int out_size) {
    const float* x  = (const float*)d_in[0];
    const float* gW = (const float*)d_in[1];
    const float* gb = (const float*)d_in[2];
    const float* eW = (const float*)d_in[3];
    const float* eb = (const float*)d_in[4];
    float* out = (float*)d_out;

    const int NT = in_sizes[0] / D_IN;   // 32768

    cudaFuncSetAttribute(moe_gemm_f16, cudaFuncAttributeMaxDynamicSharedMemorySize, SM_SZ);

    prep_kernel<<<CONV_BLOCKS + (NT + 15) / 16, 256>>>(x, gW, gb, eW, out, NT);
    moe_gemm_f16<<<NCTAS, 256, SM_SZ>>>(eb, out);
}

// round 17
// speedup vs baseline: 1.0232x; 1.0232x over previous
#include <cuda_runtime.h>
#include <cuda_fp16.h>
#include <math.h>
#include <stdint.h>

#define D_IN   768
#define D_OUT  256
#define NEXP   8
#define NT_MAX 32768
#define NCTAS  296                 // 148 SMs x 2

// ---------------- device scratch (no allocs; zero-initialized at load) -------
__device__ int    g_cnt[NEXP];
__device__ int    g_ticket;
__device__ int    g_done;
__device__ int    g_tok[NEXP * NT_MAX];
__device__ float  g_wt [NEXP * NT_MAX];
__device__ __half g_xh [NT_MAX * D_IN];              // x in fp16 (48 MB)
__device__ __half g_Wh [NEXP * D_OUT * D_IN];        // W in fp16, transposed [e][n][k]

__device__ __forceinline__ uint32_t smem_u32(const void* p) {
    uint32_t a;
    asm("{ .reg .u64 t; cvta.to.shared.u64 t, %1; cvt.u32.u64 %0, t; }" : "=r"(a) : "l"(p));
    return a;
}

// ---------------- kernel 1 (merged): convert W  +  gate + zero-out ----------
// R15 form + high-MLP gate loop (all 6 x loads issued before any FMA).
#define CONV_BLOCKS (NEXP * (D_IN / 32) * (D_OUT / 32))   // 1536
#define GW_PITCH 772

__global__ __launch_bounds__(256)
void prep_kernel(const float* __restrict__ x,
                 const float* __restrict__ gW,
                 const float* __restrict__ gb,
                 const float* __restrict__ eW,
                 float* __restrict__ out,
                 int NT) {
    const int tid = threadIdx.x;

    if (blockIdx.x < CONV_BLOCKS) {
        __shared__ float t[32][33];
        int idx = blockIdx.x;
        int e   = idx / 192;
        int rem = idx - e * 192;
        int k0  = (rem >> 3) * 32;
        int n0  = (rem & 7) * 32;
        int tx = tid & 31, ty = tid >> 5;   // 32 x 8
        const float* W = eW + (size_t)e * D_IN * D_OUT;
        __half* Wh = g_Wh + (size_t)e * D_OUT * D_IN;
#pragma unroll
        for (int j = 0; j < 4; j++)
            t[ty + j * 8][tx] = W[(size_t)(k0 + ty + j * 8) * D_OUT + n0 + tx];
        __syncthreads();
#pragma unroll
        for (int j = 0; j < 4; j++)
            Wh[(size_t)(n0 + ty + j * 8) * D_IN + k0 + tx] =
                __float2half_rn(t[tx][ty + j * 8]);
        return;
    }

    __shared__ float sWt[NEXP * GW_PITCH];   // transposed [e][k], padded pitch
    for (int i = tid; i < D_IN * NEXP; i += 256)
        sWt[(i & 7) * GW_PITCH + (i >> 3)] = gW[i];
    __syncthreads();

    int warp = tid >> 5, lane = tid & 31;
    int token = (blockIdx.x - CONV_BLOCKS) * 8 + warp;
    if (token >= NT) return;

    {
        float4 z = make_float4(0.f, 0.f, 0.f, 0.f);
        float4* orow = (float4*)(out + (size_t)token * D_OUT);
        orow[lane]      = z;
        orow[lane + 32] = z;
    }

    const float4* xr4 = (const float4*)(x + (size_t)token * D_IN);
    uint2* xo = (uint2*)(g_xh + (size_t)token * D_IN);

    // load entire row first: 6 independent float4 loads (MLP=6)
    float4 v[6];
#pragma unroll
    for (int j = 0; j < 6; j++) v[j] = xr4[lane + j * 32];

    float acc[NEXP];
#pragma unroll
    for (int e = 0; e < NEXP; e++) acc[e] = 0.f;

#pragma unroll
    for (int j = 0; j < 6; j++) {
        const int k = (lane + j * 32) * 4;
#pragma unroll
        for (int e = 0; e < NEXP; e++) {
            const float* w = &sWt[e * GW_PITCH + k];
            acc[e] = fmaf(v[j].x, w[0], acc[e]);
            acc[e] = fmaf(v[j].y, w[1], acc[e]);
            acc[e] = fmaf(v[j].z, w[2], acc[e]);
            acc[e] = fmaf(v[j].w, w[3], acc[e]);
        }
    }
#pragma unroll
    for (int j = 0; j < 6; j++) {
        __half2 h0 = __floats2half2_rn(v[j].x, v[j].y);
        __half2 h1 = __floats2half2_rn(v[j].z, v[j].w);
        uint2 u;
        u.x = *(uint32_t*)&h0;  u.y = *(uint32_t*)&h1;
        xo[lane + j * 32] = u;
    }

#pragma unroll
    for (int off = 16; off > 0; off >>= 1)
#pragma unroll
        for (int e = 0; e < NEXP; e++)
            acc[e] += __shfl_xor_sync(0xffffffffu, acc[e], off);

    if (lane == 0) {
        float l[NEXP];
#pragma unroll
        for (int e = 0; e < NEXP; e++) l[e] = acc[e] + gb[e];
        float m = l[0];
#pragma unroll
        for (int e = 1; e < NEXP; e++) m = fmaxf(m, l[e]);
        float s = 0.f, w[NEXP];
#pragma unroll
        for (int e = 0; e < NEXP; e++) { w[e] = __expf(l[e] - m); s += w[e]; }
        float inv = 1.f / s;
        int i0 = 0;
#pragma unroll
        for (int e = 1; e < NEXP; e++) if (l[e] > l[i0]) i0 = e;
        int i1 = (i0 == 0) ? 1 : 0;
#pragma unroll
        for (int e = 0; e < NEXP; e++) if (e != i0 && l[e] > l[i1]) i1 = e;

        int p0 = atomicAdd(&g_cnt[i0], 1);
        g_tok[i0 * NT_MAX + p0] = token;  g_wt[i0 * NT_MAX + p0] = w[i0] * inv;
        int p1 = atomicAdd(&g_cnt[i1], 1);
        g_tok[i1 * NT_MAX + p1] = token;  g_wt[i1 * NT_MAX + p1] = w[i1] * inv;
    }
}

// ---------------- kernel 2: persistent FP16 GEMM (exact R10 — frozen) -------
#define BKS      64
#define NSTAGE   (D_IN / BKS)     // 12
#define PSTAGES  3
#define A_STAGE  18432            // 128 * 144
#define B_STAGE  18432
#define STAGE_SZ (A_STAGE + B_STAGE)
#define SM_SZ    (PSTAGES * STAGE_SZ)             // 110592

#define CP_ASYNC_Z(dst, src, sz) \
    asm volatile("cp.async.cg.shared.global [%0], [%1], 16, %2;" \
                 :: "r"(dst), "l"(src), "r"(sz) : "memory")
#define CP_ASYNC16(dst, src) \
    asm volatile("cp.async.cg.shared.global [%0], [%1], 16;" \
                 :: "r"(dst), "l"(src) : "memory")
#define CP_COMMIT()  asm volatile("cp.async.commit_group;" ::: "memory")
#define CP_WAIT(n)   asm volatile("cp.async.wait_group %0;" :: "n"(n) : "memory")

#define LDSM_X4(r0, r1, r2, r3, addr) \
    asm volatile("ldmatrix.sync.aligned.m8n8.x4.shared.b16 {%0,%1,%2,%3}, [%4];" \
                 : "=r"(r0), "=r"(r1), "=r"(r2), "=r"(r3) : "r"(addr))

__global__ __launch_bounds__(256, 2)
void moe_gemm_f16(const float* __restrict__ eb, float* __restrict__ out) {
    extern __shared__ __align__(1024) char smem[];
    const uint32_t sb = smem_u32(smem);
    __shared__ int sTicket;

    const int tid  = threadIdx.x;
    const int wid  = tid >> 5;
    const int lane = tid & 31;
    const int wm = wid >> 1, wn = wid & 1;        // 4m x 2n
    const int grp = lane >> 2, tig = lane & 3;

    int cnts[NEXP], pfx[NEXP + 1];
    pfx[0] = 0;
#pragma unroll
    for (int e = 0; e < NEXP; e++) {
        cnts[e] = g_cnt[e];
        pfx[e + 1] = pfx[e] + 2 * ((cnts[e] + 127) >> 7);
    }
    const int totalTiles = pfx[NEXP];

    const uint32_t aRow = (uint32_t)(wm * 32 + (lane & 15));
    const uint32_t aCol = (uint32_t)((lane >> 4) * 8);
    const uint32_t bRow = (uint32_t)(wn * 64 + (lane & 7) + (lane >> 4) * 8);
    const uint32_t bCol = (uint32_t)(((lane >> 3) & 1) * 8);

    const char* xhBase = (const char*)g_xh;
    const char* whBase = (const char*)g_Wh;

    uint32_t aoff[4], adst[4], asz[4], boff[4], bdst[4];

    auto setupTile = [&](int ticket, int& e, int& mbase, int& nbase, int& cnt) {
        e = 0;
#pragma unroll
        for (int k = 1; k < NEXP; k++) if (ticket >= pfx[k]) e = k;
        const int local = ticket - pfx[e];
        nbase = (local & 1) * 128;
        mbase = (local >> 1) * 128;
        cnt   = cnts[e];
#pragma unroll
        for (int i = 0; i < 4; i++) {
            int c = tid + i * 256;
            int r = c >> 3, q = c & 7;
            int grow = mbase + r;
            bool v = grow < cnt;
            aoff[i] = (uint32_t)((v ? (size_t)g_tok[e * NT_MAX + grow] * D_IN : 0) * 2 + q * 16);
            adst[i] = sb + (uint32_t)(r * 144 + q * 16);
            asz[i]  = v ? 16u : 0u;
        }
#pragma unroll
        for (int i = 0; i < 4; i++) {
            int c = tid + i * 256;
            int n = c >> 3, q = c & 7;
            boff[i] = (uint32_t)((((size_t)e * D_OUT + nbase + n) * D_IN) * 2 + q * 16);
            bdst[i] = sb + (uint32_t)(A_STAGE + n * 144 + q * 16);
        }
    };
    auto issue = [&](int s, int sl) {
        const uint32_t so = (uint32_t)(sl * STAGE_SZ);
        const uint32_t k0 = (uint32_t)(s * BKS * 2);
#pragma unroll
        for (int i = 0; i < 4; i++)
            CP_ASYNC_Z(adst[i] + so, xhBase + aoff[i] + k0, asz[i]);
#pragma unroll
        for (int i = 0; i < 4; i++)
            CP_ASYNC16(bdst[i] + so, whBase + boff[i] + k0);
    };

    if (tid == 0) sTicket = atomicAdd(&g_ticket, 1);
    __syncthreads();
    int ticket = sTicket;
    int curE = 0, curM = 0, curN = 0, curCnt = 0;
    bool have = ticket < totalTiles;
    if (have) {
        setupTile(ticket, curE, curM, curN, curCnt);
        issue(0, 0); CP_COMMIT();
        issue(1, 1); CP_COMMIT();
    }

    while (have) {
        float acc[2][8][4];
#pragma unroll
        for (int mi = 0; mi < 2; mi++)
#pragma unroll
            for (int ni = 0; ni < 8; ni++)
#pragma unroll
                for (int c = 0; c < 4; c++) acc[mi][ni][c] = 0.f;

        int slot = 0, wslot = PSTAGES - 1;
        for (int t = 0; t < NSTAGE; t++) {
            CP_WAIT(PSTAGES - 2);
            __syncthreads();

            const uint32_t aBase = sb + (uint32_t)(slot * STAGE_SZ);
            const uint32_t bBase = aBase + A_STAGE;

#pragma unroll
            for (int kk = 0; kk < BKS; kk += 16) {
                uint32_t a[2][4];
#pragma unroll
                for (int mi = 0; mi < 2; mi++) {
                    uint32_t addr = aBase + (aRow + mi * 16) * 144 + (aCol + kk) * 2;
                    LDSM_X4(a[mi][0], a[mi][1], a[mi][2], a[mi][3], addr);
                }
                uint32_t b[8][2];
#pragma unroll
                for (int nip = 0; nip < 4; nip++) {
                    uint32_t addr = bBase + (bRow + nip * 16) * 144 + (bCol + kk) * 2;
                    LDSM_X4(b[nip*2][0], b[nip*2][1], b[nip*2+1][0], b[nip*2+1][1], addr);
                }
#pragma unroll
                for (int ni = 0; ni < 8; ni++)
#pragma unroll
                    for (int mi = 0; mi < 2; mi++) {
                        asm volatile(
                            "mma.sync.aligned.m16n8k16.row.col.f32.f16.f16.f32 "
                            "{%0,%1,%2,%3}, {%4,%5,%6,%7}, {%8,%9}, {%0,%1,%2,%3};"
                            : "+f"(acc[mi][ni][0]), "+f"(acc[mi][ni][1]),
                              "+f"(acc[mi][ni][2]), "+f"(acc[mi][ni][3])
                            : "r"(a[mi][0]), "r"(a[mi][1]), "r"(a[mi][2]), "r"(a[mi][3]),
                              "r"(b[ni][0]), "r"(b[ni][1]));
                    }
            }

            if (t + PSTAGES - 1 < NSTAGE) issue(t + PSTAGES - 1, wslot);
            CP_COMMIT();
            if (++slot == PSTAGES) slot = 0;
            if (++wslot == PSTAGES) wslot = 0;
        }

        // claim next tile; prefetch its prologue BEFORE the epilogue.
        __syncthreads();
        if (tid == 0) sTicket = atomicAdd(&g_ticket, 1);
        __syncthreads();
        int nextTicket = sTicket;
        bool haveNext = nextTicket < totalTiles;
        int nE = 0, nM = 0, nN = 0, nCnt = 0;
        if (haveNext) {
            setupTile(nextTicket, nE, nM, nN, nCnt);
            issue(0, 0); CP_COMMIT();
            issue(1, 1); CP_COMMIT();
        }

        // epilogue for current tile (overlaps next-tile DRAM latency)
        {
            float2 bias[8];
#pragma unroll
            for (int ni = 0; ni < 8; ni++)
                bias[ni] = *(const float2*)(eb + curE * D_OUT + curN + wn * 64 + ni * 8 + tig * 2);

#pragma unroll
            for (int mi = 0; mi < 2; mi++) {
#pragma unroll
                for (int h = 0; h < 2; h++) {
                    int grow = curM + wm * 32 + mi * 16 + grp + h * 8;
                    bool valid = grow < curCnt;
                    int   token = valid ? g_tok[curE * NT_MAX + grow] : 0;
                    float w     = valid ? g_wt [curE * NT_MAX + grow] : 0.f;
                    float* orow = out + (size_t)token * D_OUT + curN + wn * 64;
#pragma unroll
                    for (int ni = 0; ni < 8; ni++) {
                        float v0 = w * (acc[mi][ni][h * 2]     + bias[ni].x);
                        float v1 = w * (acc[mi][ni][h * 2 + 1] + bias[ni].y);
                        float p0 = __shfl_xor_sync(0xffffffffu, v0, 1);
                        float p1 = __shfl_xor_sync(0xffffffffu, v1, 1);
                        if (valid && !(tig & 1)) {
                            asm volatile("red.global.add.v4.f32 [%0], {%1, %2, %3, %4};"
                                         :: "l"(orow + ni * 8 + (tig & 2) * 2),
                                            "f"(v0), "f"(v1), "f"(p0), "f"(p1) : "memory");
                        }
                    }
                }
            }
        }

        curE = nE; curM = nM; curN = nN; curCnt = nCnt;
        have = haveNext;
    }

    // self-reset for next graph replay: last CTA clears state.
    __syncthreads();
    if (tid == 0) {
        int d = atomicAdd(&g_done, 1);
        if (d == NCTAS - 1) {
#pragma unroll
            for (int e = 0; e < NEXP; e++) g_cnt[e] = 0;
            g_ticket = 0;
            g_done = 0;
        }
    }
}

// ---------------- launch ----------------
extern "C" void kernel_launch(void* const* d_in, const int* in_sizes, int n_in,
                              void* d_out, int out_size) {
    const float* x  = (const float*)d_in[0];
    const float* gW = (const float*)d_in[1];
    const float* gb = (const float*)d_in[2];
    const float* eW = (const float*)d_in[3];
    const float* eb = (const float*)d_in[4];
    float* out = (float*)d_out;

    const int NT = in_sizes[0] / D_IN;   // 32768

    cudaFuncSetAttribute(moe_gemm_f16, cudaFuncAttributeMaxDynamicSharedMemorySize, SM_SZ);

    prep_kernel<<<CONV_BLOCKS + (NT + 7) / 8, 256>>>(x, gW, gb, eW, out, NT);
    moe_gemm_f16<<<NCTAS, 256, SM_SZ>>>(eb, out);
}